// round 12
// baseline (speedup 1.0000x reference)
#include <cuda_runtime.h>
#include <cstdint>

#define BB 20
#define LL 20
#define VV 100000
#define NPB (LL * LL)        // 400 elements per batch
#define PAD_LO 288
#define PAD_HI 192

__device__ float    g_part[BB];   // per-batch partial losses
__device__ unsigned g_count;      // zero-init ticket; reset by last block

// ---------------------------------------------------------------------------
// 20 classic blocks x 128 threads; block b owns batch b end-to-end.
//   Gather: 400 scattered loads into LOCAL smem (lowest per-SM L1tex pressure
//   of any layout: 400 lines/SM). Labels read directly (one line, broadcast).
//   DP: warp 0 runs the 29-step anti-diagonal wavefront for its batch
//   (16-wide segment, lane c owns DP columns 2c+1, 2c+2; one shfl per step).
//   Tail: threadFenceReduction pattern -- STG partial, fence, ticket atomic;
//   ticket==19 block fences, sums the 20 partials in FIXED order
//   (deterministic), writes out, resets the counter for the next replay.
// ---------------------------------------------------------------------------
__global__ void __launch_bounds__(128) calcs_batch_kernel(
    const float* __restrict__ topic_prob,
    const int*   __restrict__ hard_label,
    float*       __restrict__ out)
{
    __shared__ float4 s_buf4[(PAD_LO + NPB + PAD_HI) / 4];
    __shared__ float  s_val;
    float* s_P = ((float*)s_buf4) + PAD_LO;

    const int tid = threadIdx.x;
    const int b   = blockIdx.x;

    // ---- gather this batch's 400 elements into local smem ----
    #pragma unroll
    for (int it = 0; it < 4; ++it) {
        const int rel = tid + it * 128;
        if (rel < NPB) {
            const int j = rel / LL;
            const int k = rel % LL;
            const int lab = __ldg(&hard_label[b * LL + k]);   // one line, bcast
            const int idx = lab < 0 ? 0 : (lab > (VV - 1) ? (VV - 1) : lab);
            s_P[rel] = __ldg(&topic_prob[(size_t)(b * LL + j) * VV + idx]);
        }
    }
    __syncthreads();

    // ---- DP: warp 0 only ----
    if (tid < 32) {
        const int lane = tid;
        const int sub  = lane & 15;
        const int c    = sub;

        const int lab = (lane < LL) ? __ldg(&hard_label[b * LL + lane]) : -1;
        const unsigned bal = __ballot_sync(0xFFFFFFFFu, (lane < LL) && (lab >= 0))
                             & 0xFFFFFu;
        const int len = __popc(bal);

        const int  base  = -18 * c - LL;          // s_P index at t=0
        const bool capA  = (2 * c + 1 == len);
        const bool capB  = (2 * c + 2 == len);
        const bool valid = (c < 10) && (lane < 16);   // only segment 0 computes

        float prevA = 0.0f, prevB = 0.0f, dleft = 0.0f, result = 0.0f;

        if (bal == 0xFFFFFu) {
            // fast path: all masks set (always for this data)
            #pragma unroll
            for (int t = 1; t <= LL + 9; ++t) {
                float left = __shfl_up_sync(0xFFFFFFFFu, prevB, 1, 16);
                if (sub == 0) left = 0.0f;
                const float diag = dleft;
                dleft = left;

                const int  j   = t - c;
                const bool act = valid && (j >= 1) && (j <= LL);

                const float2 p2 = *(const float2*)(s_P + base + t * LL);

                const float Ma = fmaxf(left, prevA);
                const float vA = fmaf(p2.x, diag + 1.0f - Ma, Ma);
                const float Mb = fmaxf(vA, prevB);
                const float vB = fmaf(p2.y, prevA + 1.0f - Mb, Mb);

                if (act) {
                    if (j == len) {
                        if (capA) result = vA;
                        if (capB) result = vB;
                    }
                    prevA = vA;
                    prevB = vB;
                }
            }
        } else {
            // general path: per-cell mask zeroing
            const unsigned bitA = (bal >> (2 * c)) & 1u;
            const unsigned bitB = (bal >> (2 * c + 1)) & 1u;
            #pragma unroll
            for (int t = 1; t <= LL + 9; ++t) {
                float left = __shfl_up_sync(0xFFFFFFFFu, prevB, 1, 16);
                if (sub == 0) left = 0.0f;
                const float diag = dleft;
                dleft = left;

                const int  j   = t - c;
                const bool act = valid && (j >= 1) && (j <= LL);
                const int  js  = (j < 1) ? 1 : (j > LL ? LL : j);
                const unsigned mj = (bal >> (js - 1)) & 1u;

                const float2 p2 = *(const float2*)(s_P + base + t * LL);

                const float Ma = fmaxf(left, prevA);
                float vA = fmaf(p2.x, diag + 1.0f - Ma, Ma);
                vA = (mj & bitA) ? vA : 0.0f;
                const float Mb = fmaxf(vA, prevB);
                float vB = fmaf(p2.y, prevA + 1.0f - Mb, Mb);
                vB = (mj & bitB) ? vB : 0.0f;

                if (act) {
                    if (j == len) {
                        if (capA) result = vA;
                        if (capB) result = vB;
                    }
                    prevA = vA;
                    prevB = vB;
                }
            }
        }

        // this batch's loss
        if (len > 0) {
            if ((capA || capB) && valid)
                s_val = -logf(result / (float)len);
        } else if (lane == 0) {
            s_val = -logf(0.0f / 0.0f);       // 0/0 -> nan, matches reference
        }
        __syncwarp();

        if (lane == 0) {
            g_part[b] = s_val;
            __threadfence();                  // partial visible before ticket
            const unsigned ticket = atomicAdd(&g_count, 1u);
            if (ticket == BB - 1) {
                __threadfence();              // acquire all partials
                float s = 0.0f;
                #pragma unroll
                for (int r = 0; r < BB; ++r)  // fixed order: deterministic
                    s += g_part[r];
                out[0] = s * (1.0f / (float)BB);
                g_count = 0u;                 // reset for next graph replay
            }
        }
    }
}

extern "C" void kernel_launch(void* const* d_in, const int* in_sizes, int n_in,
                              void* d_out, int out_size) {
    const float* topic_prob = (const float*)d_in[0];
    const int*   hard_label = (const int*)d_in[1];
    float*       out        = (float*)d_out;
    calcs_batch_kernel<<<BB, 128>>>(topic_prob, hard_label, out);
}